// round 14
// baseline (speedup 1.0000x reference)
#include <cuda_runtime.h>
#include <cuda_bf16.h>
#include <cstdint>

#define BB   4
#define NQ   16384
#define MM   4096
#define CC   256
#define BN   (BB*NQ)

// ---------------- scratch (static device memory; no allocations) ----------------
__device__ float4 g_w[BN];          // per-query 3 weights
__device__ int4   g_i[BN];          // per-query 3 neighbor indices
__device__ float  g_ft[BB*MM*CC];   // transposed features (B, M, C), 16.8 MB

static __device__ __forceinline__ float f_inf() { return __int_as_float(0x7f800000); }

// Squared norm with LLVM DAGCombiner contraction order (bit-matches reference):
//   t = fma(x,x, round(y*y));  su = fma(z,z, t)
static __device__ __forceinline__ float norm2_llvm(float x, float y, float z) {
    return fmaf(z, z, fmaf(x, x, __fmul_rn(y, y)));
}

// ---------------- kernel 1: transpose feats (B,C,M) -> (B,M,C) ----------------
__global__ void __launch_bounds__(256) tr_kernel(const float* __restrict__ f) {
    __shared__ float t[32][33];
    int b  = blockIdx.z;
    int m0 = blockIdx.x * 32;
    int c0 = blockIdx.y * 32;
    const float* fb = f + (size_t)b * CC * MM;
#pragma unroll
    for (int i = threadIdx.y; i < 32; i += 8)
        t[i][threadIdx.x] = fb[(size_t)(c0 + i) * MM + m0 + threadIdx.x];
    __syncthreads();
    float* fo = g_ft + (size_t)b * MM * CC;
#pragma unroll
    for (int i = threadIdx.y; i < 32; i += 8)
        fo[(size_t)(m0 + i) * CC + c0 + threadIdx.x] = t[threadIdx.x][i];
}

// ---------------- kernel 2: 3-NN + inverse-distance weights ----------------
// Block = 256 threads, 128 queries. Warps 0-3 scan candidates [0,2048) for
// queries 0..127; warps 4-7 scan [2048,4096) for the same queries. Partial
// top-3s merged via smem (strict-< insert keeps lower-index half first on ties,
// matching top_k stability). All 4096 points staged once in 64KB dynamic smem;
// inner loads are warp-uniform broadcasts.
__device__ __forceinline__ void knn_upd(float d2, int gj,
                                        float& b0, float& b1, float& b2,
                                        int& i0, int& i1, int& i2) {
    if (d2 < b2) {
        if (d2 < b1) {
            b2 = b1; i2 = i1;
            if (d2 < b0) { b1 = b0; i1 = i0; b0 = d2; i0 = gj; }
            else         { b1 = d2; i1 = gj; }
        } else { b2 = d2; i2 = gj; }
    }
}

// exact path: reference-rounded d2 (asc FMA dot; (su+kk) - 2*dot)
#define KNN_PROC(kp, gj) do {                                                  \
    float _dt = fmaf((kp).z, uz, fmaf((kp).y, uy, __fmul_rn((kp).x, ux)));     \
    float _d2 = __fadd_rn(__fadd_rn(su, (kp).w), -__fmul_rn(2.0f, _dt));       \
    knn_upd(_d2, (gj), b0, b1, b2, i0, i1, i2);                                \
} while (0)

#define SCREEN1(vv, kp, gj) do {                                               \
    if ((vv) < thr) {                                                          \
        KNN_PROC(kp, gj);                                                      \
        thr = __fadd_rn(__fadd_rn(b2, -su), 6e-6f);                            \
    }                                                                          \
} while (0)

__global__ void __launch_bounds__(256, 3) knn_kernel(const float* __restrict__ unknown,
                                                     const float* __restrict__ known) {
    extern __shared__ float4 sk[];   // 4096 float4 = 64KB (x,y,z,|k|^2)

    int tid  = threadIdx.x;
    int lq   = tid & 127;            // query slot within block
    int half = tid >> 7;             // candidate half (0 or 1)
    int qid  = blockIdx.x * 128 + lq;
    int b    = qid >> 14;            // / NQ
    const float* kb = known + (size_t)b * MM * 3;

    float ux = unknown[(size_t)qid * 3 + 0];
    float uy = unknown[(size_t)qid * 3 + 1];
    float uz = unknown[(size_t)qid * 3 + 2];
    float su = norm2_llvm(ux, uy, uz);
    float nux = __fmul_rn(-2.0f, ux);
    float nuy = __fmul_rn(-2.0f, uy);
    float nuz = __fmul_rn(-2.0f, uz);

    // stage all 4096 points
    for (int p = tid; p < MM; p += 256) {
        float kx = kb[(size_t)p * 3 + 0];
        float ky = kb[(size_t)p * 3 + 1];
        float kz = kb[(size_t)p * 3 + 2];
        sk[p] = make_float4(kx, ky, kz, norm2_llvm(kx, ky, kz));
    }
    __syncthreads();

    float b0 = f_inf(), b1 = f_inf(), b2 = f_inf();
    int   i0 = 0, i1 = 0, i2 = 0;
    float thr = f_inf();

    const float4* skh  = sk + half * 2048;
    int           gbase = half * 2048;

    for (int j = 0; j < 2048; j += 8) {
        float4 c0 = skh[j + 0];
        float4 c1 = skh[j + 1];
        float4 c2 = skh[j + 2];
        float4 c3 = skh[j + 3];
        float4 c4 = skh[j + 4];
        float4 c5 = skh[j + 5];
        float4 c6 = skh[j + 6];
        float4 c7 = skh[j + 7];
        float v0 = fmaf(c0.x, nux, fmaf(c0.y, nuy, fmaf(c0.z, nuz, c0.w)));
        float v1 = fmaf(c1.x, nux, fmaf(c1.y, nuy, fmaf(c1.z, nuz, c1.w)));
        float v2 = fmaf(c2.x, nux, fmaf(c2.y, nuy, fmaf(c2.z, nuz, c2.w)));
        float v3 = fmaf(c3.x, nux, fmaf(c3.y, nuy, fmaf(c3.z, nuz, c3.w)));
        float v4 = fmaf(c4.x, nux, fmaf(c4.y, nuy, fmaf(c4.z, nuz, c4.w)));
        float v5 = fmaf(c5.x, nux, fmaf(c5.y, nuy, fmaf(c5.z, nuz, c5.w)));
        float v6 = fmaf(c6.x, nux, fmaf(c6.y, nuy, fmaf(c6.z, nuz, c6.w)));
        float v7 = fmaf(c7.x, nux, fmaf(c7.y, nuy, fmaf(c7.z, nuz, c7.w)));
        float vm = fminf(fminf(fminf(v0, v1), fminf(v2, v3)),
                         fminf(fminf(v4, v5), fminf(v6, v7)));
        if (vm < thr) {   // rare slow path, per-candidate gated, ascending index
            SCREEN1(v0, c0, gbase + j + 0);
            SCREEN1(v1, c1, gbase + j + 1);
            SCREEN1(v2, c2, gbase + j + 2);
            SCREEN1(v3, c3, gbase + j + 3);
            SCREEN1(v4, c4, gbase + j + 4);
            SCREEN1(v5, c5, gbase + j + 5);
            SCREEN1(v6, c6, gbase + j + 6);
            SCREEN1(v7, c7, gbase + j + 7);
        }
    }

    // merge: half1 publishes its partial top-3; half0 inserts (ties -> half0 wins,
    // which is correct since half0 indices are smaller)
    __syncthreads();
    if (half == 1) {
        ((float4*)sk)[lq]       = make_float4(b0, b1, b2, 0.0f);
        ((int4*)sk)[128 + lq]   = make_int4(i0, i1, i2, 0);
    }
    __syncthreads();
    if (half == 0) {
        float4 pd = ((float4*)sk)[lq];
        int4   pi = ((int4*)sk)[128 + lq];
        knn_upd(pd.x, pi.x, b0, b1, b2, i0, i1, i2);
        knn_upd(pd.y, pi.y, b0, b1, b2, i0, i1, i2);
        knn_upd(pd.z, pi.z, b0, b1, b2, i0, i1, i2);

        // weights: dist = sqrt(max(d2,0)); r = 1/(dist+eps); w = r / sum(r)
        float dd0 = sqrtf(fmaxf(b0, 0.0f));
        float dd1 = sqrtf(fmaxf(b1, 0.0f));
        float dd2 = sqrtf(fmaxf(b2, 0.0f));
        float r0 = __fdiv_rn(1.0f, __fadd_rn(dd0, 1e-8f));
        float r1 = __fdiv_rn(1.0f, __fadd_rn(dd1, 1e-8f));
        float r2 = __fdiv_rn(1.0f, __fadd_rn(dd2, 1e-8f));
        float ws = __fadd_rn(__fadd_rn(r0, r1), r2);
        g_w[qid] = make_float4(__fdiv_rn(r0, ws), __fdiv_rn(r1, ws),
                               __fdiv_rn(r2, ws), 0.0f);
        g_i[qid] = make_int4(i0, i1, i2, 0);
    }
}

// ---------------- kernel 3: coalesced gather + blend, transposed write ----------------
__global__ void __launch_bounds__(256) gather_kernel(float* __restrict__ out) {
    __shared__ float  tile[CC][33];   // [c][q], pad to kill bank conflicts
    __shared__ float4 sw[32];
    __shared__ int4   si[32];

    int blk = blockIdx.x;
    int b   = blk >> 9;          // NQ/32 = 512 blocks per batch
    int n0  = (blk & 511) << 5;
    int tid = threadIdx.x;

    if (tid < 32) {
        sw[tid] = g_w[b * NQ + n0 + tid];
        si[tid] = g_i[b * NQ + n0 + tid];
    }
    __syncthreads();

    const float* ftb = g_ft + (size_t)b * MM * CC;
    int c = tid;
#pragma unroll 4
    for (int q = 0; q < 32; q++) {
        int4   jj = si[q];
        float4 ww = sw[q];
        float f0 = __ldg(&ftb[(size_t)jj.x * CC + c]);
        float f1 = __ldg(&ftb[(size_t)jj.y * CC + c]);
        float f2 = __ldg(&ftb[(size_t)jj.z * CC + c]);
        tile[c][q] = fmaf(f2, ww.z, fmaf(f1, ww.y, __fmul_rn(f0, ww.x)));
    }
    __syncthreads();

    float* ob = out + (size_t)b * CC * NQ;
    int wrp = tid >> 5, lane = tid & 31;
#pragma unroll
    for (int r = wrp; r < CC; r += 8)
        ob[(size_t)r * NQ + n0 + lane] = tile[r][lane];
}

// ---------------- launch ----------------
extern "C" void kernel_launch(void* const* d_in, const int* in_sizes, int n_in,
                              void* d_out, int out_size) {
    const float* unknown = (const float*)d_in[0];   // (B, n, 3)
    const float* known   = (const float*)d_in[1];   // (B, m, 3)
    const float* feats   = (const float*)d_in[2];   // (B, C, m)
    float* out = (float*)d_out;                     // (B, C, n)

    static bool attr_done = false;
    if (!attr_done) {
        cudaFuncSetAttribute(knn_kernel,
                             cudaFuncAttributeMaxDynamicSharedMemorySize,
                             MM * (int)sizeof(float4));
        attr_done = true;
    }

    dim3 tb(32, 8);
    dim3 tg(MM / 32, CC / 32, BB);
    tr_kernel<<<tg, tb>>>(feats);

    knn_kernel<<<BN / 128, 256, MM * sizeof(float4)>>>(unknown, known);

    gather_kernel<<<BN / 32, 256>>>(out);
}

// round 15
// speedup vs baseline: 1.0019x; 1.0019x over previous
#include <cuda_runtime.h>
#include <cuda_bf16.h>
#include <cstdint>

#define BB   4
#define NQ   16384
#define MM   4096
#define CC   256
#define BN   (BB*NQ)

// ---------------- scratch (static device memory; no allocations) ----------------
__device__ float4 g_w[BN];          // per-query 3 weights
__device__ int4   g_i[BN];          // per-query 3 neighbor indices
__device__ float  g_ft[BB*MM*CC];   // transposed features (B, M, C), 16.8 MB

static __device__ __forceinline__ float f_inf() { return __int_as_float(0x7f800000); }

// Squared norm with LLVM DAGCombiner contraction order (bit-matches reference):
//   t = fma(x,x, round(y*y));  su = fma(z,z, t)
static __device__ __forceinline__ float norm2_llvm(float x, float y, float z) {
    return fmaf(z, z, fmaf(x, x, __fmul_rn(y, y)));
}

// ---------------- kernel 1: transpose feats (B,C,M) -> (B,M,C) ----------------
__global__ void __launch_bounds__(256) tr_kernel(const float* __restrict__ f) {
    __shared__ float t[32][33];
    int b  = blockIdx.z;
    int m0 = blockIdx.x * 32;
    int c0 = blockIdx.y * 32;
    const float* fb = f + (size_t)b * CC * MM;
#pragma unroll
    for (int i = threadIdx.y; i < 32; i += 8)
        t[i][threadIdx.x] = fb[(size_t)(c0 + i) * MM + m0 + threadIdx.x];
    __syncthreads();
    float* fo = g_ft + (size_t)b * MM * CC;
#pragma unroll
    for (int i = threadIdx.y; i < 32; i += 8)
        fo[(size_t)(m0 + i) * CC + c0 + threadIdx.x] = t[threadIdx.x][i];
}

// ---------------- kernel 2: 3-NN + inverse-distance weights ----------------
// Block = 256 threads, 128 queries. Warps 0-3 scan candidates [0,2048) for
// queries 0..127; warps 4-7 scan [2048,4096) for the same queries. Partial
// top-3s merged via smem (strict-< insert keeps lower-index half first on ties,
// matching top_k stability). All 4096 points staged once in 64KB dynamic smem;
// inner loads are warp-uniform broadcasts.
__device__ __forceinline__ void knn_upd(float d2, int gj,
                                        float& b0, float& b1, float& b2,
                                        int& i0, int& i1, int& i2) {
    if (d2 < b2) {
        if (d2 < b1) {
            b2 = b1; i2 = i1;
            if (d2 < b0) { b1 = b0; i1 = i0; b0 = d2; i0 = gj; }
            else         { b1 = d2; i1 = gj; }
        } else { b2 = d2; i2 = gj; }
    }
}

// exact path: reference-rounded d2 (asc FMA dot; (su+kk) - 2*dot)
#define KNN_PROC(kp, gj) do {                                                  \
    float _dt = fmaf((kp).z, uz, fmaf((kp).y, uy, __fmul_rn((kp).x, ux)));     \
    float _d2 = __fadd_rn(__fadd_rn(su, (kp).w), -__fmul_rn(2.0f, _dt));       \
    knn_upd(_d2, (gj), b0, b1, b2, i0, i1, i2);                                \
} while (0)

#define SCREEN1(vv, kp, gj) do {                                               \
    if ((vv) < thr) {                                                          \
        KNN_PROC(kp, gj);                                                      \
        thr = __fadd_rn(__fadd_rn(b2, -su), 6e-6f);                            \
    }                                                                          \
} while (0)

__global__ void __launch_bounds__(256, 3) knn_kernel(const float* __restrict__ unknown,
                                                     const float* __restrict__ known) {
    extern __shared__ float4 sk[];   // 4096 float4 = 64KB (x,y,z,|k|^2)

    int tid  = threadIdx.x;
    int lq   = tid & 127;            // query slot within block
    int half = tid >> 7;             // candidate half (0 or 1)
    int qid  = blockIdx.x * 128 + lq;
    int b    = qid >> 14;            // / NQ
    const float* kb = known + (size_t)b * MM * 3;

    float ux = unknown[(size_t)qid * 3 + 0];
    float uy = unknown[(size_t)qid * 3 + 1];
    float uz = unknown[(size_t)qid * 3 + 2];
    float su = norm2_llvm(ux, uy, uz);
    float nux = __fmul_rn(-2.0f, ux);
    float nuy = __fmul_rn(-2.0f, uy);
    float nuz = __fmul_rn(-2.0f, uz);

    // stage all 4096 points
    for (int p = tid; p < MM; p += 256) {
        float kx = kb[(size_t)p * 3 + 0];
        float ky = kb[(size_t)p * 3 + 1];
        float kz = kb[(size_t)p * 3 + 2];
        sk[p] = make_float4(kx, ky, kz, norm2_llvm(kx, ky, kz));
    }
    __syncthreads();

    float b0 = f_inf(), b1 = f_inf(), b2 = f_inf();
    int   i0 = 0, i1 = 0, i2 = 0;
    float thr = f_inf();

    const float4* skh  = sk + half * 2048;
    int           gbase = half * 2048;

    for (int j = 0; j < 2048; j += 8) {
        float4 c0 = skh[j + 0];
        float4 c1 = skh[j + 1];
        float4 c2 = skh[j + 2];
        float4 c3 = skh[j + 3];
        float4 c4 = skh[j + 4];
        float4 c5 = skh[j + 5];
        float4 c6 = skh[j + 6];
        float4 c7 = skh[j + 7];
        float v0 = fmaf(c0.x, nux, fmaf(c0.y, nuy, fmaf(c0.z, nuz, c0.w)));
        float v1 = fmaf(c1.x, nux, fmaf(c1.y, nuy, fmaf(c1.z, nuz, c1.w)));
        float v2 = fmaf(c2.x, nux, fmaf(c2.y, nuy, fmaf(c2.z, nuz, c2.w)));
        float v3 = fmaf(c3.x, nux, fmaf(c3.y, nuy, fmaf(c3.z, nuz, c3.w)));
        float v4 = fmaf(c4.x, nux, fmaf(c4.y, nuy, fmaf(c4.z, nuz, c4.w)));
        float v5 = fmaf(c5.x, nux, fmaf(c5.y, nuy, fmaf(c5.z, nuz, c5.w)));
        float v6 = fmaf(c6.x, nux, fmaf(c6.y, nuy, fmaf(c6.z, nuz, c6.w)));
        float v7 = fmaf(c7.x, nux, fmaf(c7.y, nuy, fmaf(c7.z, nuz, c7.w)));
        float vm = fminf(fminf(fminf(v0, v1), fminf(v2, v3)),
                         fminf(fminf(v4, v5), fminf(v6, v7)));
        if (vm < thr) {   // rare slow path, per-candidate gated, ascending index
            SCREEN1(v0, c0, gbase + j + 0);
            SCREEN1(v1, c1, gbase + j + 1);
            SCREEN1(v2, c2, gbase + j + 2);
            SCREEN1(v3, c3, gbase + j + 3);
            SCREEN1(v4, c4, gbase + j + 4);
            SCREEN1(v5, c5, gbase + j + 5);
            SCREEN1(v6, c6, gbase + j + 6);
            SCREEN1(v7, c7, gbase + j + 7);
        }
    }

    // merge: half1 publishes its partial top-3; half0 inserts (ties -> half0 wins,
    // which is correct since half0 indices are smaller)
    __syncthreads();
    if (half == 1) {
        ((float4*)sk)[lq]       = make_float4(b0, b1, b2, 0.0f);
        ((int4*)sk)[128 + lq]   = make_int4(i0, i1, i2, 0);
    }
    __syncthreads();
    if (half == 0) {
        float4 pd = ((float4*)sk)[lq];
        int4   pi = ((int4*)sk)[128 + lq];
        knn_upd(pd.x, pi.x, b0, b1, b2, i0, i1, i2);
        knn_upd(pd.y, pi.y, b0, b1, b2, i0, i1, i2);
        knn_upd(pd.z, pi.z, b0, b1, b2, i0, i1, i2);

        // weights: dist = sqrt(max(d2,0)); r = 1/(dist+eps); w = r / sum(r)
        float dd0 = sqrtf(fmaxf(b0, 0.0f));
        float dd1 = sqrtf(fmaxf(b1, 0.0f));
        float dd2 = sqrtf(fmaxf(b2, 0.0f));
        float r0 = __fdiv_rn(1.0f, __fadd_rn(dd0, 1e-8f));
        float r1 = __fdiv_rn(1.0f, __fadd_rn(dd1, 1e-8f));
        float r2 = __fdiv_rn(1.0f, __fadd_rn(dd2, 1e-8f));
        float ws = __fadd_rn(__fadd_rn(r0, r1), r2);
        g_w[qid] = make_float4(__fdiv_rn(r0, ws), __fdiv_rn(r1, ws),
                               __fdiv_rn(r2, ws), 0.0f);
        g_i[qid] = make_int4(i0, i1, i2, 0);
    }
}

// ---------------- kernel 3: coalesced gather + blend, transposed write ----------------
__global__ void __launch_bounds__(256) gather_kernel(float* __restrict__ out) {
    __shared__ float  tile[CC][33];   // [c][q], pad to kill bank conflicts
    __shared__ float4 sw[32];
    __shared__ int4   si[32];

    int blk = blockIdx.x;
    int b   = blk >> 9;          // NQ/32 = 512 blocks per batch
    int n0  = (blk & 511) << 5;
    int tid = threadIdx.x;

    if (tid < 32) {
        sw[tid] = g_w[b * NQ + n0 + tid];
        si[tid] = g_i[b * NQ + n0 + tid];
    }
    __syncthreads();

    const float* ftb = g_ft + (size_t)b * MM * CC;
    int c = tid;
#pragma unroll 4
    for (int q = 0; q < 32; q++) {
        int4   jj = si[q];
        float4 ww = sw[q];
        float f0 = __ldg(&ftb[(size_t)jj.x * CC + c]);
        float f1 = __ldg(&ftb[(size_t)jj.y * CC + c]);
        float f2 = __ldg(&ftb[(size_t)jj.z * CC + c]);
        tile[c][q] = fmaf(f2, ww.z, fmaf(f1, ww.y, __fmul_rn(f0, ww.x)));
    }
    __syncthreads();

    float* ob = out + (size_t)b * CC * NQ;
    int wrp = tid >> 5, lane = tid & 31;
#pragma unroll
    for (int r = wrp; r < CC; r += 8)
        ob[(size_t)r * NQ + n0 + lane] = tile[r][lane];
}

// ---------------- launch ----------------
extern "C" void kernel_launch(void* const* d_in, const int* in_sizes, int n_in,
                              void* d_out, int out_size) {
    const float* unknown = (const float*)d_in[0];   // (B, n, 3)
    const float* known   = (const float*)d_in[1];   // (B, m, 3)
    const float* feats   = (const float*)d_in[2];   // (B, C, m)
    float* out = (float*)d_out;                     // (B, C, n)

    static bool attr_done = false;
    if (!attr_done) {
        cudaFuncSetAttribute(knn_kernel,
                             cudaFuncAttributeMaxDynamicSharedMemorySize,
                             MM * (int)sizeof(float4));
        attr_done = true;
    }

    dim3 tb(32, 8);
    dim3 tg(MM / 32, CC / 32, BB);
    tr_kernel<<<tg, tb>>>(feats);

    knn_kernel<<<BN / 128, 256, MM * sizeof(float4)>>>(unknown, known);

    gather_kernel<<<BN / 32, 256>>>(out);
}

// round 16
// speedup vs baseline: 1.2151x; 1.2128x over previous
#include <cuda_runtime.h>
#include <cuda_bf16.h>
#include <cstdint>

#define BB   4
#define NQ   16384
#define MM   4096
#define CC   256
#define BN   (BB*NQ)

// ---------------- scratch (static device memory; no allocations) ----------------
__device__ float4 g_w[BN];          // per-query 3 weights
__device__ int4   g_i[BN];          // per-query 3 neighbor indices
__device__ float  g_ft[BB*MM*CC];   // transposed features (B, M, C), 16.8 MB

static __device__ __forceinline__ float f_inf() { return __int_as_float(0x7f800000); }

// Squared norm with LLVM DAGCombiner contraction order (bit-matches reference):
//   t = fma(x,x, round(y*y));  su = fma(z,z, t)
static __device__ __forceinline__ float norm2_llvm(float x, float y, float z) {
    return fmaf(z, z, fmaf(x, x, __fmul_rn(y, y)));
}

// packed f32x2 fma (sm_103a): d = a*b + c per 32-bit lane, rn each lane
union f2u { unsigned long long u; float2 f; };
#define FMA2(d, a, b, c) \
    asm("fma.rn.f32x2 %0, %1, %2, %3;" : "=l"(d) : "l"(a), "l"(b), "l"(c))

// ---------------- kernel 1: transpose feats (B,C,M) -> (B,M,C) ----------------
__global__ void __launch_bounds__(256) tr_kernel(const float* __restrict__ f) {
    __shared__ float t[32][33];
    int b  = blockIdx.z;
    int m0 = blockIdx.x * 32;
    int c0 = blockIdx.y * 32;
    const float* fb = f + (size_t)b * CC * MM;
#pragma unroll
    for (int i = threadIdx.y; i < 32; i += 8)
        t[i][threadIdx.x] = fb[(size_t)(c0 + i) * MM + m0 + threadIdx.x];
    __syncthreads();
    float* fo = g_ft + (size_t)b * MM * CC;
#pragma unroll
    for (int i = threadIdx.y; i < 32; i += 8)
        fo[(size_t)(m0 + i) * CC + c0 + threadIdx.x] = t[threadIdx.x][i];
}

// ---------------- kernel 2: 3-NN + inverse-distance weights ----------------
// R13 structure (256 blocks x 256 thr, one query/thread, 2-chunk SoA staging,
// all blocks resident). Screen runs on packed f32x2 (FFMA2): 8 candidates per
// threshold check = 4 independent packed chains. Exact (rare) path keeps the
// reference-rounded d2 bit-for-bit:
//   su,kk = fma(z,z, fma(x,x, y*y));  dot = fma(z,uz, fma(y,uy, x*ux));
//   d2    = (su + kk) - 2*dot
__device__ __forceinline__ void knn_upd(float d2, int gj,
                                        float& b0, float& b1, float& b2,
                                        int& i0, int& i1, int& i2) {
    if (d2 < b2) {
        if (d2 < b1) {
            b2 = b1; i2 = i1;
            if (d2 < b0) { b1 = b0; i1 = i0; b0 = d2; i0 = gj; }
            else         { b1 = d2; i1 = gj; }
        } else { b2 = d2; i2 = gj; }
    }
}

#define KNN_PROC2(kx, ky, kz, kw, gj) do {                                     \
    float _dt = fmaf((kz), uz, fmaf((ky), uy, __fmul_rn((kx), ux)));           \
    float _d2 = __fadd_rn(__fadd_rn(su, (kw)), -__fmul_rn(2.0f, _dt));         \
    knn_upd(_d2, (gj), b0, b1, b2, i0, i1, i2);                                \
} while (0)

__global__ void __launch_bounds__(256) knn_kernel(const float* __restrict__ unknown,
                                                  const float* __restrict__ known) {
    // SoA chunk of 2048 candidates (32 KB): packed-pair friendly
    __shared__ __align__(16) float skx[2048];
    __shared__ __align__(16) float sky[2048];
    __shared__ __align__(16) float skz[2048];
    __shared__ __align__(16) float skk[2048];

    int qid = blockIdx.x * 256 + threadIdx.x;   // all threads of a block share batch b
    int b   = qid >> 14;                        // / NQ
    const float* kb = known + (size_t)b * MM * 3;

    float ux = unknown[(size_t)qid * 3 + 0];
    float uy = unknown[(size_t)qid * 3 + 1];
    float uz = unknown[(size_t)qid * 3 + 2];
    float su = norm2_llvm(ux, uy, uz);
    float nux = __fmul_rn(-2.0f, ux);
    float nuy = __fmul_rn(-2.0f, uy);
    float nuz = __fmul_rn(-2.0f, uz);
    f2u nux2, nuy2, nuz2;
    nux2.f = make_float2(nux, nux);
    nuy2.f = make_float2(nuy, nuy);
    nuz2.f = make_float2(nuz, nuz);

    float b0 = f_inf(), b1 = f_inf(), b2 = f_inf();
    int   i0 = 0, i1 = 0, i2 = 0;
    float thr = f_inf();   // screen threshold in v-space: (b2 - su) + margin

    for (int ch = 0; ch < 2; ch++) {
        int base = ch * 2048;
        __syncthreads();
        for (int p = threadIdx.x; p < 2048; p += 256) {
            float kx = kb[(size_t)(base + p) * 3 + 0];
            float ky = kb[(size_t)(base + p) * 3 + 1];
            float kz = kb[(size_t)(base + p) * 3 + 2];
            skx[p] = kx; sky[p] = ky; skz[p] = kz;
            skk[p] = norm2_llvm(kx, ky, kz);
        }
        __syncthreads();

        for (int j = 0; j < 2048; j += 8) {
            f2u x0, x1, x2, x3, y0, y1, y2, y3, z0, z1, z2, z3, w0, w1, w2, w3;
            ulonglong2 t;
            t = *(const ulonglong2*)(skx + j);     x0.u = t.x; x1.u = t.y;
            t = *(const ulonglong2*)(skx + j + 4); x2.u = t.x; x3.u = t.y;
            t = *(const ulonglong2*)(sky + j);     y0.u = t.x; y1.u = t.y;
            t = *(const ulonglong2*)(sky + j + 4); y2.u = t.x; y3.u = t.y;
            t = *(const ulonglong2*)(skz + j);     z0.u = t.x; z1.u = t.y;
            t = *(const ulonglong2*)(skz + j + 4); z2.u = t.x; z3.u = t.y;
            t = *(const ulonglong2*)(skk + j);     w0.u = t.x; w1.u = t.y;
            t = *(const ulonglong2*)(skk + j + 4); w2.u = t.x; w3.u = t.y;

            f2u v0, v1, v2, v3;
            FMA2(v0.u, z0.u, nuz2.u, w0.u);
            FMA2(v1.u, z1.u, nuz2.u, w1.u);
            FMA2(v2.u, z2.u, nuz2.u, w2.u);
            FMA2(v3.u, z3.u, nuz2.u, w3.u);
            FMA2(v0.u, y0.u, nuy2.u, v0.u);
            FMA2(v1.u, y1.u, nuy2.u, v1.u);
            FMA2(v2.u, y2.u, nuy2.u, v2.u);
            FMA2(v3.u, y3.u, nuy2.u, v3.u);
            FMA2(v0.u, x0.u, nux2.u, v0.u);
            FMA2(v1.u, x1.u, nux2.u, v1.u);
            FMA2(v2.u, x2.u, nux2.u, v2.u);
            FMA2(v3.u, x3.u, nux2.u, v3.u);

            float m0 = fminf(fminf(v0.f.x, v0.f.y), fminf(v1.f.x, v1.f.y));
            float m1 = fminf(fminf(v2.f.x, v2.f.y), fminf(v3.f.x, v3.f.y));
            if (fminf(m0, m1) < thr) {   // rare: exact reference-rounded inserts
                KNN_PROC2(x0.f.x, y0.f.x, z0.f.x, w0.f.x, base + j + 0);
                KNN_PROC2(x0.f.y, y0.f.y, z0.f.y, w0.f.y, base + j + 1);
                KNN_PROC2(x1.f.x, y1.f.x, z1.f.x, w1.f.x, base + j + 2);
                KNN_PROC2(x1.f.y, y1.f.y, z1.f.y, w1.f.y, base + j + 3);
                KNN_PROC2(x2.f.x, y2.f.x, z2.f.x, w2.f.x, base + j + 4);
                KNN_PROC2(x2.f.y, y2.f.y, z2.f.y, w2.f.y, base + j + 5);
                KNN_PROC2(x3.f.x, y3.f.x, z3.f.x, w3.f.x, base + j + 6);
                KNN_PROC2(x3.f.y, y3.f.y, z3.f.y, w3.f.y, base + j + 7);
                thr = __fadd_rn(__fadd_rn(b2, -su), 6e-6f);
            }
        }
    }

    // weights: dist = sqrt(max(d2,0)); r = 1/(dist+eps); w = r / sum(r)
    float dd0 = sqrtf(fmaxf(b0, 0.0f));
    float dd1 = sqrtf(fmaxf(b1, 0.0f));
    float dd2 = sqrtf(fmaxf(b2, 0.0f));
    float r0 = __fdiv_rn(1.0f, __fadd_rn(dd0, 1e-8f));
    float r1 = __fdiv_rn(1.0f, __fadd_rn(dd1, 1e-8f));
    float r2 = __fdiv_rn(1.0f, __fadd_rn(dd2, 1e-8f));
    float ws = __fadd_rn(__fadd_rn(r0, r1), r2);
    g_w[qid] = make_float4(__fdiv_rn(r0, ws), __fdiv_rn(r1, ws),
                           __fdiv_rn(r2, ws), 0.0f);
    g_i[qid] = make_int4(i0, i1, i2, 0);
}

// ---------------- kernel 3: coalesced gather + blend, transposed write ----------------
__global__ void __launch_bounds__(256) gather_kernel(float* __restrict__ out) {
    __shared__ float  tile[CC][33];   // [c][q], pad to kill bank conflicts
    __shared__ float4 sw[32];
    __shared__ int4   si[32];

    int blk = blockIdx.x;
    int b   = blk >> 9;          // NQ/32 = 512 blocks per batch
    int n0  = (blk & 511) << 5;
    int tid = threadIdx.x;

    if (tid < 32) {
        sw[tid] = g_w[b * NQ + n0 + tid];
        si[tid] = g_i[b * NQ + n0 + tid];
    }
    __syncthreads();

    const float* ftb = g_ft + (size_t)b * MM * CC;
    int c = tid;
#pragma unroll 4
    for (int q = 0; q < 32; q++) {
        int4   jj = si[q];
        float4 ww = sw[q];
        float f0 = __ldg(&ftb[(size_t)jj.x * CC + c]);
        float f1 = __ldg(&ftb[(size_t)jj.y * CC + c]);
        float f2 = __ldg(&ftb[(size_t)jj.z * CC + c]);
        tile[c][q] = fmaf(f2, ww.z, fmaf(f1, ww.y, __fmul_rn(f0, ww.x)));
    }
    __syncthreads();

    float* ob = out + (size_t)b * CC * NQ;
    int wrp = tid >> 5, lane = tid & 31;
#pragma unroll
    for (int r = wrp; r < CC; r += 8)
        ob[(size_t)r * NQ + n0 + lane] = tile[r][lane];
}

// ---------------- launch ----------------
extern "C" void kernel_launch(void* const* d_in, const int* in_sizes, int n_in,
                              void* d_out, int out_size) {
    const float* unknown = (const float*)d_in[0];   // (B, n, 3)
    const float* known   = (const float*)d_in[1];   // (B, m, 3)
    const float* feats   = (const float*)d_in[2];   // (B, C, m)
    float* out = (float*)d_out;                     // (B, C, n)

    dim3 tb(32, 8);
    dim3 tg(MM / 32, CC / 32, BB);
    tr_kernel<<<tg, tb>>>(feats);

    knn_kernel<<<BN / 256, 256>>>(unknown, known);

    gather_kernel<<<BN / 32, 256>>>(out);
}